// round 6
// baseline (speedup 1.0000x reference)
#include <cuda_runtime.h>

// Problem constants (fixed: midis_out is (16, 11, 65536) fp32, LST=64)
#define NB      16
#define NI      11
#define NT      65536
#define LSTLEN  64
#define CHUNK   512
#define NTB     (CHUNK / LSTLEN)    // 8 time-blocks per CTA
#define THREADS 256
#define NWARP   (THREADS / 32)
#define NCHUNK  (NT / CHUNK)        // 128
#define VEC4    (NI * CHUNK / 4)    // 1408 float4 per tile
#define NTASK   (NI * NTB)          // 88 time-block tasks
#define NGRP    (NTASK / 4)         // 22 groups of 4 tasks

typedef unsigned long long u64;

// ---- Blackwell packed-f32 helpers (add.rn.f32x2 / mul.rn.f32x2 are sm_100a) ----
__device__ __forceinline__ u64 pk2(float x, float y) {
    u64 r; asm("mov.b64 %0, {%1, %2};" : "=l"(r) : "f"(x), "f"(y)); return r;
}
__device__ __forceinline__ float2 up2(u64 v) {
    float2 r; asm("mov.b64 {%0, %1}, %2;" : "=f"(r.x), "=f"(r.y) : "l"(v)); return r;
}
__device__ __forceinline__ u64 add2_(u64 a, u64 b) {
    u64 r; asm("add.rn.f32x2 %0, %1, %2;" : "=l"(r) : "l"(a), "l"(b)); return r;
}
__device__ __forceinline__ u64 mul2_(u64 a, u64 b) {
    u64 r; asm("mul.rn.f32x2 %0, %1, %2;" : "=l"(r) : "l"(a), "l"(b)); return r;
}

__device__ __forceinline__ void ce(float& a, float& b) {
    const float lo = fminf(a, b), hi = fmaxf(a, b);
    a = lo; b = hi;
}

// Optimal 11-input sorting network (35 CE, depth 8), ascending.
__device__ __forceinline__ void sort11(float z[NI]) {
    ce(z[0],z[9]); ce(z[1],z[6]); ce(z[2],z[4]); ce(z[3],z[7]); ce(z[5],z[8]);
    ce(z[0],z[1]); ce(z[3],z[5]); ce(z[4],z[10]); ce(z[6],z[9]); ce(z[7],z[8]);
    ce(z[1],z[3]); ce(z[2],z[5]); ce(z[4],z[7]); ce(z[8],z[10]);
    ce(z[0],z[4]); ce(z[1],z[2]); ce(z[3],z[7]); ce(z[5],z[9]); ce(z[6],z[8]);
    ce(z[0],z[1]); ce(z[2],z[6]); ce(z[4],z[5]); ce(z[7],z[8]); ce(z[9],z[10]);
    ce(z[2],z[4]); ce(z[3],z[6]); ce(z[5],z[7]); ce(z[8],z[9]);
    ce(z[1],z[2]); ce(z[3],z[4]); ce(z[5],z[6]); ce(z[7],z[8]);
    ce(z[2],z[3]); ce(z[4],z[5]); ce(z[6],z[7]);
}

// Exact sparsemax over 11 values; returns NEGATED tau (destroys z).
// cond_k: 1 + k*z_(k) > csum_k holds exactly for k <= k_z (prefix-monotone),
// so k_z = last k with cond true and csum_{k_z} = cs at that k.
// -tau = (1 - csum_{k_z}) / k_z.
__device__ __forceinline__ float sparsemax11_negtau(float z[NI]) {
    sort11(z);
    float cs = 0.0f, sel = 0.0f, cnt = 1.0f;
    #pragma unroll
    for (int k = 1; k <= NI; ++k) {
        const float zk = z[NI - k];                    // k-th largest
        cs += zk;
        const bool c = fmaf((float)k, zk, 1.0f) > cs;  // always true at k=1
        sel = c ? cs : sel;
        cnt = c ? (float)k : cnt;
    }
    return __fdividef(1.0f - sel, cnt);
}

__global__ __launch_bounds__(THREADS, 6)
void multiply_sparsemax_kernel(const float* __restrict__ in,
                               float* __restrict__ out)
{
    __shared__ __align__(16) float xs[NI * CHUNK];  // 22528 B tile
    __shared__ float ntau_time[NTASK];              // NEGATED tau per (inst, 64-block)

    const int tid  = threadIdx.x;
    const int wid  = tid >> 5;
    const int lane = tid & 31;

    const int b = blockIdx.x / NCHUNK;
    const int c = blockIdx.x % NCHUNK;
    const unsigned base = (unsigned)(b * NI) * NT + (unsigned)(c * CHUNK);

    // ---- Load tile: 11 rows x 512 floats, float4-coalesced ----
    #pragma unroll
    for (int idx = tid; idx < VEC4; idx += THREADS) {
        const int i  = idx >> 7;
        const int t4 = idx & 127;
        *(float4*)(xs + i * CHUNK + t4 * 4) =
            *((const float4*)(in + base + (unsigned)(i * NT)) + t4);
    }
    __syncthreads();

    // ---- Phase A: tau over 64-length time blocks ----
    // 4 tasks/warp (8-lane segments, 8 elems/lane). Michelot from the safe
    // warm start tau0 = max-1 (tau* >= max-1 always). Updates are idempotent
    // at the fixed point: 3 unconditional iterations + a checked guard loop
    // (usually exits on its first check) -> exact and branch-light.
    {
        const int seg = lane >> 3;
        const int sl  = lane & 7;
        for (int g = wid; g < NGRP; g += NWARP) {
            const int task = g * 4 + seg;
            const float* p = xs + (task >> 3) * CHUNK + (task & 7) * LSTLEN + sl * 8;
            const float4 v0 = *(const float4*)p;
            const float4 v1 = *(const float4*)(p + 4);
            const float z0 = v0.x, z1 = v0.y, z2 = v0.z, z3 = v0.w;
            const float z4 = v1.x, z5 = v1.y, z6 = v1.z, z7 = v1.w;

            float m = fmaxf(fmaxf(fmaxf(z0, z1), fmaxf(z2, z3)),
                            fmaxf(fmaxf(z4, z5), fmaxf(z6, z7)));
            #pragma unroll
            for (int o = 4; o; o >>= 1)
                m = fmaxf(m, __shfl_xor_sync(0xFFFFFFFFu, m, o));

            float tau = m - 1.0f;
            float cf  = 0.0f;

            #pragma unroll
            for (int it = 0; it < 3; ++it) {
                float ss = 0.0f; cf = 0.0f;
                if (z0 > tau) { ss += z0; cf += 1.0f; }
                if (z1 > tau) { ss += z1; cf += 1.0f; }
                if (z2 > tau) { ss += z2; cf += 1.0f; }
                if (z3 > tau) { ss += z3; cf += 1.0f; }
                if (z4 > tau) { ss += z4; cf += 1.0f; }
                if (z5 > tau) { ss += z5; cf += 1.0f; }
                if (z6 > tau) { ss += z6; cf += 1.0f; }
                if (z7 > tau) { ss += z7; cf += 1.0f; }
                #pragma unroll
                for (int o = 4; o; o >>= 1) {
                    ss += __shfl_xor_sync(0xFFFFFFFFu, ss, o);
                    cf += __shfl_xor_sync(0xFFFFFFFFu, cf, o);
                }
                tau = __fdividef(ss - 1.0f, cf);
            }

            int k = (int)cf;
            #pragma unroll 1
            for (;;) {
                float ss = 0.0f, c2 = 0.0f;
                if (z0 > tau) { ss += z0; c2 += 1.0f; }
                if (z1 > tau) { ss += z1; c2 += 1.0f; }
                if (z2 > tau) { ss += z2; c2 += 1.0f; }
                if (z3 > tau) { ss += z3; c2 += 1.0f; }
                if (z4 > tau) { ss += z4; c2 += 1.0f; }
                if (z5 > tau) { ss += z5; c2 += 1.0f; }
                if (z6 > tau) { ss += z6; c2 += 1.0f; }
                if (z7 > tau) { ss += z7; c2 += 1.0f; }
                #pragma unroll
                for (int o = 4; o; o >>= 1) {
                    ss += __shfl_xor_sync(0xFFFFFFFFu, ss, o);
                    c2 += __shfl_xor_sync(0xFFFFFFFFu, c2, o);
                }
                const int kn = (int)c2;
                const bool conv = (kn >= k);         // support stable
                if (__all_sync(0xFFFFFFFFu, conv)) break;
                if (!conv) { tau = __fdividef(ss - 1.0f, c2); k = kn; }
            }
            if (sl == 0) ntau_time[task] = -tau;     // store negated
        }
    }

    // ---- Phase B: instrument sparsemax (sort + count-form scan, branch-free).
    //      Depends only on xs (already synced) -> runs BEFORE the barrier so
    //      Phase-A warp skew is hidden under this compute. ----
    const int t0 = tid * 2;                  // 2 adjacent columns
    float nta, ntb;
    {
        float za[NI], zb[NI];
        #pragma unroll
        for (int i = 0; i < NI; ++i) {
            const float2 v = *(const float2*)(xs + i * CHUNK + t0);
            za[i] = v.x; zb[i] = v.y;
        }
        nta = sparsemax11_negtau(za);        // destroys za
        ntb = sparsemax11_negtau(zb);        // destroys zb
    }

    __syncthreads();                         // ntau_time now visible

    // ---- Phase C: fused epilogue, packed f32x2 math, straight to gmem ----
    {
        const int blkb = wid;                // t0>>6 == tid>>5 (uniform/warp)
        const u64 nti = pk2(nta, ntb);
        const float* px = xs + t0;
        float* po = out + base + (unsigned)t0;
        #pragma unroll
        for (int i = 0; i < NI; ++i) {
            const float tn = ntau_time[i * NTB + blkb];   // broadcast LDS (-tau)
            const u64 ntt = pk2(tn, tn);
            const u64 v   = *(const u64*)(px + i * CHUNK);
            float2 d1 = up2(add2_(v, nti));   // v - tau_inst (packed)
            float2 d2 = up2(add2_(v, ntt));   // v - tau_time (packed)
            d1.x = fmaxf(d1.x, 0.0f); d1.y = fmaxf(d1.y, 0.0f);
            d2.x = fmaxf(d2.x, 0.0f); d2.y = fmaxf(d2.y, 0.0f);
            const u64 r = mul2_(pk2(d1.x, d1.y), pk2(d2.x, d2.y));
            *(u64*)(po + (unsigned)(i * NT)) = r;
        }
    }
}

extern "C" void kernel_launch(void* const* d_in, const int* in_sizes, int n_in,
                              void* d_out, int out_size)
{
    const float* in = (const float*)d_in[0];
    float* out = (float*)d_out;
    multiply_sparsemax_kernel<<<NB * NCHUNK, THREADS>>>(in, out);
}